// round 12
// baseline (speedup 1.0000x reference)
#include <cuda_runtime.h>

// Problem constants
#define Bn     32
#define Cn     40
#define Ln     16000
#define Kn     128
#define Sn     125      // LS / STRIDE
#define STILE  32       // s-values per block
#define NTILES 4        // ceil(125/32)
#define NOUT   (Bn * Cn * Sn)   // 160000 outputs (real part)

#define XSEG   132               // 128 data + 4 pad floats per segment

// ---- packed f32x2 helpers (Blackwell sm_103a) ----
#define FMA2(acc, a, b) \
    asm("fma.rn.f32x2 %0, %1, %2, %0;" : "+l"(acc) : "l"(a), "l"(b))
#define ADD2(acc, a) \
    asm("add.rn.f32x2 %0, %0, %1;" : "+l"(acc) : "l"(a))
#define PACKDUP(out, f) \
    asm("mov.b64 %0, {%1, %1};" : "=l"(out) : "f"(f))
#define UNPACK2(lo, hi, in) \
    asm("mov.b64 {%0, %1}, %2;" : "=f"(lo), "=f"(hi) : "l"(in))

// ---------------- fast mode-0 kernel (real part only) ----------------
// Grid (4, 32), 1024 threads = 32 warps.
//   warp w: pg = w&3  -> channel-pair group (5 pairs = 10 channels)
//           sq = w>>2 -> s-quad (4 s-values)
//   lane:   k  = lane>>2 -> 16-tap K-slice (8 slices)
//           si = lane&3  -> s within quad
// K-slice reduction is done IN-WARP via 3 shfl.bfly steps over lane bits
// 2..4 -> no partials smem, no second barrier, no epilogue phase.
//
// smem:
//   kp : 20 pairs x [8 slices x 18 float2] (16 taps + 2 pad per slice so the
//        8 per-warp kernel addresses land on disjoint bank groups), 23040 B
//        kp[p][m] = (kr[2p][127-m], kr[2p+1][127-m])  at f2 idx
//        p*144 + (m>>4)*18 + (m&15)
//   xs : 32 segments x 132 floats (pad -> conflict-free float4), 16896 B
#define KP_F2       (20 * 144)          // 2880 float2
#define XS_FLOATS   (32 * XSEG)         // 4224
#define SMEMB_FAST  ((2 * KP_F2 + XS_FLOATS) * 4)   // 39936 B

__global__ __launch_bounds__(1024, 1)
void isac_conv_fast(const float* __restrict__ x,
                    const float* __restrict__ kr,
                    float* __restrict__ out)
{
    extern __shared__ float sm[];
    float2* kp = (float2*)sm;
    float*  xs = sm + 2 * KP_F2;

    const int tid   = threadIdx.x;
    const int stile = blockIdx.x;
    const int b     = blockIdx.y;

    // ---- x tile: segment L holds x[128*(s0+L)-127 .. 128*(s0+L)] ----
    const int gstart = stile * (STILE * Kn) - 127;   // negative only for tile 0
    const float* xb = x + b * Ln;
    #pragma unroll
    for (int i = 0; i < 4; i++) {
        const int j = tid + i * 1024;
        int g = gstart + j;
        if (g < 0)        g += Ln;
        else if (g >= Ln) g -= Ln;
        xs[(j >> 7) * XSEG + (j & 127)] = xb[g];
    }

    // ---- kernel repack (tap-reversed, pair-packed, slice-padded) ----
    #pragma unroll
    for (int i = 0; i < 3; i++) {
        const int idx = tid + i * 1024;
        if (idx < 2560) {
            const int p = idx >> 7, m = idx & 127;
            kp[p * 144 + (m >> 4) * 18 + (m & 15)] =
                make_float2(kr[(2 * p)     * Kn + (127 - m)],
                            kr[(2 * p + 1) * Kn + (127 - m)]);
        }
    }
    __syncthreads();

    // ---- compute: 5 pairs x 16-tap slice, one s per thread ----
    const int lane = tid & 31;
    const int w    = tid >> 5;
    const int pg   = w & 3;               // 5-pair group
    const int sq   = w >> 2;              // s-quad
    const int k    = lane >> 2;           // K slice (16 taps)
    const int si   = lane & 3;            // s within quad
    const int sl   = sq * 4 + si;         // s within 32-s tile

    const float4* xp = (const float4*)(xs + sl * XSEG) + k * 4;
    // ulonglong2 view: pair stride 72, slice stride 9
    const ulonglong2* kb = (const ulonglong2*)kp + (pg * 5) * 72 + k * 9;

    unsigned long long acc[5] = {0ull, 0ull, 0ull, 0ull, 0ull};

    #pragma unroll
    for (int i = 0; i < 4; i++) {          // 4 float4 = 16 taps
        const float4 xv = xp[i];
        unsigned long long x0, x1, x2, x3;
        PACKDUP(x0, xv.x); PACKDUP(x1, xv.y);
        PACKDUP(x2, xv.z); PACKDUP(x3, xv.w);
        #pragma unroll
        for (int j = 0; j < 5; j++) {
            const ulonglong2 k01 = kb[j * 72 + 2 * i];
            const ulonglong2 k23 = kb[j * 72 + 2 * i + 1];
            FMA2(acc[j], x0, k01.x);
            FMA2(acc[j], x1, k01.y);
            FMA2(acc[j], x2, k23.x);
            FMA2(acc[j], x3, k23.y);
        }
    }

    // ---- in-warp K-slice reduction: bfly over lane bits 2..4 ----
    #pragma unroll
    for (int mask = 4; mask <= 16; mask <<= 1) {
        #pragma unroll
        for (int j = 0; j < 5; j++) {
            const unsigned long long o =
                __shfl_xor_sync(0xffffffffu, acc[j], mask);
            ADD2(acc[j], o);
        }
    }

    // ---- write: lane k<5 writes pair pg*5+k for its s ----
    if (k < 5) {
        unsigned long long v;
        switch (k) {
            case 0:  v = acc[0]; break;
            case 1:  v = acc[1]; break;
            case 2:  v = acc[2]; break;
            case 3:  v = acc[3]; break;
            default: v = acc[4]; break;
        }
        float lo, hi;
        UNPACK2(lo, hi, v);
        const int p = pg * 5 + k;
        const int s = stile * STILE + sl;
        if (s < Sn) {
            out[(b * Cn + 2 * p)     * Sn + s] = lo;
            out[(b * Cn + 2 * p + 1) * Sn + s] = hi;
        }
    }
}

// ---------------- fallback (full complex) — not expected to trigger ----------------
#define KERN_FLOATS (Cn * Kn)
#define SMEMB_FB ((2 * KERN_FLOATS + 32 * XSEG) * 4)

__global__ __launch_bounds__(256)
void isac_conv_fallback(const float* __restrict__ x,
                        const float* __restrict__ kr,
                        const float* __restrict__ ki,
                        float* __restrict__ out,
                        int mode)   // 1 = planar, 2 = interleaved
{
    extern __shared__ float smem[];
    float* kr_s = smem;
    float* ki_s = smem + KERN_FLOATS;
    float* xs   = smem + 2 * KERN_FLOATS;

    const int tid = threadIdx.x, stile = blockIdx.x, b = blockIdx.y;
    #pragma unroll 4
    for (int idx = tid; idx < KERN_FLOATS; idx += 256) {
        const int c = idx >> 7, m = idx & 127;
        kr_s[idx] = kr[c * Kn + (127 - m)];
        ki_s[idx] = ki[c * Kn + (127 - m)];
    }
    const int gstart = stile * (STILE * Kn) - 127;
    const float* xb = x + b * Ln;
    #pragma unroll 4
    for (int j = tid; j < 32 * Kn; j += 256) {
        int g = gstart + j;
        if (g < 0) g += Ln; else if (g >= Ln) g -= Ln;
        xs[(j >> 7) * XSEG + (j & 127)] = xb[g];
    }
    __syncthreads();

    const int lane = tid & 31, w = tid >> 5;
    const int s = stile * STILE + lane, c0 = w * 5;
    const float4* xp  = (const float4*)(xs + lane * XSEG);
    const float4* krp = (const float4*)(kr_s + c0 * Kn);
    const float4* kip = (const float4*)(ki_s + c0 * Kn);

    float ar[5] = {0,0,0,0,0}, ai[5] = {0,0,0,0,0};
    #pragma unroll 2
    for (int m4 = 0; m4 < Kn / 4; m4++) {
        const float4 xv = xp[m4];
        #pragma unroll
        for (int cc = 0; cc < 5; cc++) {
            const float4 kv = krp[cc * (Kn / 4) + m4];
            const float4 iv = kip[cc * (Kn / 4) + m4];
            ar[cc] = fmaf(xv.x, kv.x, fmaf(xv.y, kv.y, fmaf(xv.z, kv.z, fmaf(xv.w, kv.w, ar[cc]))));
            ai[cc] = fmaf(xv.x, iv.x, fmaf(xv.y, iv.y, fmaf(xv.z, iv.z, fmaf(xv.w, iv.w, ai[cc]))));
        }
    }
    if (s < Sn) {
        if (mode == 1) {
            #pragma unroll
            for (int cc = 0; cc < 5; cc++) {
                const int idx = (b * Cn + (c0 + cc)) * Sn + s;
                out[idx] = ar[cc]; out[NOUT + idx] = ai[cc];
            }
        } else {
            float2* o2 = (float2*)out;
            #pragma unroll
            for (int cc = 0; cc < 5; cc++)
                o2[(b * Cn + (c0 + cc)) * Sn + s] = make_float2(ar[cc], ai[cc]);
        }
    }
}

extern "C" void kernel_launch(void* const* d_in, const int* in_sizes, int n_in,
                              void* d_out, int out_size)
{
    const float* x  = (const float*)d_in[0];   // (32, 1, 16000) f32
    const float* kr = (const float*)d_in[1];   // (40, 128) f32
    const float* ki = (const float*)d_in[2];   // (40, 128) f32
    float* out = (float*)d_out;

    dim3 grid(NTILES, Bn);
    if (out_size == NOUT) {
        isac_conv_fast<<<grid, 1024, SMEMB_FAST>>>(x, kr, out);
    } else {
        const int mode = (out_size == 2 * NOUT) ? 1 : 2;
        cudaFuncSetAttribute(isac_conv_fallback,
                             cudaFuncAttributeMaxDynamicSharedMemorySize, SMEMB_FB);
        isac_conv_fallback<<<grid, 256, SMEMB_FB>>>(x, kr, ki, out, mode);
    }
}